// round 12
// baseline (speedup 1.0000x reference)
#include <cuda_runtime.h>
#include <cuda_bf16.h>
#include <math.h>
#include <stdint.h>

// Problem constants
constexpr int Bb   = 2;
constexpr int Ss   = 1024;
constexpr int Hh   = 4096;
constexpr int NHq  = 32;
constexpr int NKVh = 8;
constexpr int HDd  = 128;
constexpr int MTOK = Bb * Ss;             // 2048
constexpr int QD   = NHq * HDd;           // 4096
constexpr int KVD  = NKVh * HDd;          // 1024

// ---------------- device scratch (static; allocation-free) ----------------
__device__ float          g_q[(size_t)MTOK * QD];
__device__ float          g_k[(size_t)MTOK * KVD];
__device__ float          g_v[(size_t)MTOK * KVD];
__device__ float          g_scores[(size_t)Bb * NHq * Ss * Ss];
__device__ int8_t         g_a0[(size_t)MTOK * Hh];        // activation digit 0
__device__ int8_t         g_a1[(size_t)MTOK * Hh];        // activation digit 1
__device__ int8_t         g_wq[(size_t)QD  * Hh];
__device__ int8_t         g_wk[(size_t)KVD * Hh];
__device__ int8_t         g_wv[(size_t)KVD * Hh];
__device__ int8_t         g_wo[(size_t)Hh  * QD];
__device__ __nv_bfloat16  g_vhi[(size_t)Bb * NKVh * HDd * Ss];
__device__ __nv_bfloat16  g_vlo[(size_t)Bb * NKVh * HDd * Ss];
__device__ double         g_absum[4];
__device__ float          g_gamma[4];
__device__ float2         g_rowstat[(size_t)Bb * NHq * Ss];   // (max, 1/sum) per row

// ---------------- helpers ----------------
__device__ __forceinline__ uint32_t smem_u32(const void* p) {
    uint32_t a;
    asm("{ .reg .u64 t; cvta.to.shared.u64 t, %1; cvt.u32.u64 %0, t; }" : "=r"(a) : "l"(p));
    return a;
}
__device__ __forceinline__ uint32_t packbf(float a, float b) {
    __nv_bfloat162 t = __floats2bfloat162_rn(a, b);
    return *(uint32_t*)&t;
}
__device__ __forceinline__ void mma16816(float* c, const uint32_t* a, const uint32_t* b) {
    asm volatile(
        "mma.sync.aligned.m16n8k16.row.col.f32.bf16.bf16.f32 "
        "{%0,%1,%2,%3}, {%4,%5,%6,%7}, {%8,%9}, {%0,%1,%2,%3};"
        : "+f"(c[0]), "+f"(c[1]), "+f"(c[2]), "+f"(c[3])
        : "r"(a[0]), "r"(a[1]), "r"(a[2]), "r"(a[3]), "r"(b[0]), "r"(b[1]));
}
__device__ __forceinline__ void imma16832(int* c, const uint32_t* a, const uint32_t* b) {
    asm volatile(
        "mma.sync.aligned.m16n8k32.row.col.s32.s8.s8.s32 "
        "{%0,%1,%2,%3}, {%4,%5,%6,%7}, {%8,%9}, {%0,%1,%2,%3};"
        : "+r"(c[0]), "+r"(c[1]), "+r"(c[2]), "+r"(c[3])
        : "r"(a[0]), "r"(a[1]), "r"(a[2]), "r"(a[3]), "r"(b[0]), "r"(b[1]));
}
#define CP_ASYNC16(dst, src) \
    asm volatile("cp.async.cg.shared.global [%0], [%1], 16;" :: "r"(dst), "l"(src))
#define CP_COMMIT() asm volatile("cp.async.commit_group;" ::: "memory")
#define CP_WAIT1()  asm volatile("cp.async.wait_group 1;" ::: "memory")
#define CP_WAIT0()  asm volatile("cp.async.wait_group 0;" ::: "memory")

constexpr int ST = 40;   // bf16 smem row stride (attention kernels)

// activation digit quantization: i = rint(a*4096), d1=(i+128)>>8, d0=i-256*d1
__device__ __forceinline__ void qdigits(float v, int& d0, int& d1) {
    float x = rintf(v * 4096.f);
    x = fminf(32512.f, fmaxf(-32512.f, x));
    int i = (int)x;
    d1 = (i + 128) >> 8;
    d0 = i - (d1 << 8);
}

// ---------------- gamma: abs-sum reduction (float4) ----------------
__global__ void init_kernel() {
    if (threadIdx.x < 4) g_absum[threadIdx.x] = 0.0;
}

__global__ void abssum_kernel(const float4* __restrict__ w, size_t n4, int idx) {
    float s = 0.f;
    for (size_t i = (size_t)blockIdx.x * blockDim.x + threadIdx.x; i < n4;
         i += (size_t)gridDim.x * blockDim.x) {
        float4 v = w[i];
        s += fabsf(v.x) + fabsf(v.y) + fabsf(v.z) + fabsf(v.w);
    }
    __shared__ double sh[256];
    sh[threadIdx.x] = (double)s;
    __syncthreads();
    for (int o = 128; o > 0; o >>= 1) {
        if ((int)threadIdx.x < o) sh[threadIdx.x] += sh[threadIdx.x + o];
        __syncthreads();
    }
    if (threadIdx.x == 0) atomicAdd(&g_absum[idx], sh[0]);
}

// ---------------- ternary quantization -> int8 plane ----------------
__global__ void quantize_w(const float4* __restrict__ w, char4* __restrict__ t,
                           size_t n4, int idx) {
    float gamma = (float)(g_absum[idx] / (double)(n4 * 4)) + 1e-5f;
    if (blockIdx.x == 0 && threadIdx.x == 0) g_gamma[idx] = gamma;
    for (size_t i = (size_t)blockIdx.x * blockDim.x + threadIdx.x; i < n4;
         i += (size_t)gridDim.x * blockDim.x) {
        float4 v = w[i];
        char rx = (char)(int)fminf(1.f, fmaxf(-1.f, rintf(v.x / gamma)));
        char ry = (char)(int)fminf(1.f, fmaxf(-1.f, rintf(v.y / gamma)));
        char rz = (char)(int)fminf(1.f, fmaxf(-1.f, rintf(v.z / gamma)));
        char rw = (char)(int)fminf(1.f, fmaxf(-1.f, rintf(v.w / gamma)));
        t[i] = make_char4(rx, ry, rz, rw);
    }
}

// ---------------- fp32 -> two int8 digit planes ----------------
__global__ void aquant_kernel(const float4* __restrict__ x,
                              char4* __restrict__ p0, char4* __restrict__ p1, size_t n4) {
    for (size_t i = (size_t)blockIdx.x * blockDim.x + threadIdx.x; i < n4;
         i += (size_t)gridDim.x * blockDim.x) {
        float4 f = x[i];
        int a0, a1, b0, b1, c0, c1, d0, d1;
        qdigits(f.x, a0, a1);
        qdigits(f.y, b0, b1);
        qdigits(f.z, c0, c1);
        qdigits(f.w, d0, d1);
        p0[i] = make_char4((char)a0, (char)b0, (char)c0, (char)d0);
        p1[i] = make_char4((char)a1, (char)b1, (char)c1, (char)d1);
    }
}

// ---------------- V -> transposed hi/lo bf16 planes: vt[bk][d][s] ----------------
__global__ void vsplit_kernel() {
    size_t idx = (size_t)blockIdx.x * blockDim.x + threadIdx.x;
    if (idx >= (size_t)Bb * NKVh * HDd * Ss) return;
    int s  = (int)(idx & (Ss - 1));
    int d  = (int)((idx >> 10) & 127);
    int bk = (int)(idx >> 17);
    int b  = bk >> 3, kv = bk & 7;
    float v = g_v[((size_t)(b * Ss + s)) * KVD + kv * HDd + d];
    __nv_bfloat16 h = __float2bfloat16_rn(v);
    g_vhi[idx] = h;
    g_vlo[idx] = __float2bfloat16_rn(v - __bfloat162float(h));
}

// ================= int8 IMMA projection GEMM (128x128 tile, K-chunk 64, 2-stage) =================
// C[M,N] = gamma*2^-12 * ((A0 + 256*A1)[M,K] . W[N,K]^T)
constexpr int SK      = 80;               // int8 smem row stride (conflict-free frags)
constexpr int IPL     = 128 * SK;         // bytes per plane
constexpr int GI_SMEM = 2 * 3 * IPL;      // 61440 B

__global__ __launch_bounds__(256) void gemm_imma(
    const int8_t* __restrict__ A0, const int8_t* __restrict__ A1,
    const int8_t* __restrict__ W, float* __restrict__ C,
    int N, int K, int gidx)
{
    extern __shared__ __align__(16) int8_t si[];
    const uint32_t ubase = smem_u32(si);

    const int tid  = threadIdx.x;
    const int wid  = tid >> 5;
    const int lane = tid & 31;
    const int g    = lane >> 2;
    const int t    = lane & 3;
    const int m0   = blockIdx.y * 128;
    const int n0   = blockIdx.x * 128;
    const int wrow = (wid >> 2) * 64;
    const int wcol = (wid & 3) * 32;

    // 512 16B-chunks per plane, 2 per thread
    const int r0 = (tid * 2)     >> 2, c0 = ((tid * 2)     & 3) * 16;
    const int r1 = (tid * 2 + 1) >> 2, c1 = ((tid * 2 + 1) & 3) * 16;

    int acc0[4][4][4], acc1[4][4][4];
#pragma unroll
    for (int i = 0; i < 4; i++)
#pragma unroll
        for (int j = 0; j < 4; j++)
#pragma unroll
            for (int r = 0; r < 4; r++) { acc0[i][j][r] = 0; acc1[i][j][r] = 0; }

    const int iters = K >> 6;   // K / 64

    auto issue = [&](int it, int stg) {
        const int kc = it << 6;
        uint32_t s0 = ubase + (uint32_t)(stg * 3 * IPL);
        CP_ASYNC16(s0 + r0 * SK + c0,             &A0[(size_t)(m0 + r0) * K + kc + c0]);
        CP_ASYNC16(s0 + r1 * SK + c1,             &A0[(size_t)(m0 + r1) * K + kc + c1]);
        CP_ASYNC16(s0 + IPL + r0 * SK + c0,       &A1[(size_t)(m0 + r0) * K + kc + c0]);
        CP_ASYNC16(s0 + IPL + r1 * SK + c1,       &A1[(size_t)(m0 + r1) * K + kc + c1]);
        CP_ASYNC16(s0 + 2 * IPL + r0 * SK + c0,   &W[(size_t)(n0 + r0) * K + kc + c0]);
        CP_ASYNC16(s0 + 2 * IPL + r1 * SK + c1,   &W[(size_t)(n0 + r1) * K + kc + c1]);
        CP_COMMIT();
    };

    issue(0, 0);
    for (int it = 0; it < iters; ++it) {
        const int stg = it & 1;
        if (it + 1 < iters) { issue(it + 1, stg ^ 1); CP_WAIT1(); }
        else                { CP_WAIT0(); }
        __syncthreads();

        const int8_t* sa0 = si + stg * 3 * IPL;
        const int8_t* sa1 = sa0 + IPL;
        const int8_t* sw  = sa0 + 2 * IPL;

#pragma unroll
        for (int kk = 0; kk < 64; kk += 32) {
            uint32_t a0f[4][4], a1f[4][4], bf[4][2];
#pragma unroll
            for (int mt = 0; mt < 4; mt++) {
                int m = wrow + mt * 16 + g;
                a0f[mt][0] = *(const uint32_t*)&sa0[(m    ) * SK + kk + 4 * t     ];
                a0f[mt][1] = *(const uint32_t*)&sa0[(m + 8) * SK + kk + 4 * t     ];
                a0f[mt][2] = *(const uint32_t*)&sa0[(m    ) * SK + kk + 4 * t + 16];
                a0f[mt][3] = *(const uint32_t*)&sa0[(m + 8) * SK + kk + 4 * t + 16];
                a1f[mt][0] = *(const uint32_t*)&sa1[(m    ) * SK + kk + 4 * t     ];
                a1f[mt][1] = *(const uint32_t*)&sa1[(m + 8) * SK + kk + 4 * t     ];
                a1f[mt][2] = *(const uint32_t*)&sa1[(m    ) * SK + kk + 4 * t + 16];
                a1f[mt][3] = *(const uint32_t*)&sa1[(m + 8) * SK + kk + 4 * t + 16];
            }
#pragma unroll
            for (int nt = 0; nt < 4; nt++) {
                int n = wcol + nt * 8 + g;
                bf[nt][0] = *(const uint32_t*)&sw[n * SK + kk + 4 * t     ];
                bf[nt][1] = *(const uint32_t*)&sw[n * SK + kk + 4 * t + 16];
            }
#pragma unroll
            for (int mt = 0; mt < 4; mt++)
#pragma unroll
                for (int nt = 0; nt < 4; nt++) {
                    imma16832(acc0[mt][nt], a0f[mt], bf[nt]);
                    imma16832(acc1[mt][nt], a1f[mt], bf[nt]);
                }
        }
        __syncthreads();
    }

    const float scale = g_gamma[gidx] * (1.f / 4096.f);
#pragma unroll
    for (int mt = 0; mt < 4; mt++) {
#pragma unroll
        for (int nt = 0; nt < 4; nt++) {
            int m = m0 + wrow + mt * 16 + g;
            int n = n0 + wcol + nt * 8 + 2 * t;
            float2 lo = make_float2(
                ((float)acc0[mt][nt][0] + 256.f * (float)acc1[mt][nt][0]) * scale,
                ((float)acc0[mt][nt][1] + 256.f * (float)acc1[mt][nt][1]) * scale);
            float2 hi = make_float2(
                ((float)acc0[mt][nt][2] + 256.f * (float)acc1[mt][nt][2]) * scale,
                ((float)acc0[mt][nt][3] + 256.f * (float)acc1[mt][nt][3]) * scale);
            *(float2*)&C[(size_t)m * N + n]       = lo;
            *(float2*)&C[(size_t)(m + 8) * N + n] = hi;
        }
    }
}

// ---------------- RoPE (in place), uses position_ids ----------------
__global__ void rope_kernel(float* __restrict__ x, int nheads,
                            const int* __restrict__ pos_ids) {
    size_t idx = (size_t)blockIdx.x * blockDim.x + threadIdx.x;
    size_t total = (size_t)MTOK * nheads * 64;
    if (idx >= total) return;
    int d = (int)(idx & 63);
    size_t th = idx >> 6;
    int head = (int)(th % nheads);
    size_t tok = th / nheads;
    int pos = pos_ids[tok];
    float inv_freq = 1.0f / powf(10000.0f, (float)d * (1.0f / 64.0f));
    float fr = (float)pos * inv_freq;
    float s, c;
    sincosf(fr, &s, &c);
    float* base = x + tok * ((size_t)nheads * HDd) + (size_t)head * HDd;
    float x1 = base[d], x2 = base[d + 64];
    base[d]      = x1 * c - x2 * s;
    base[d + 64] = x2 * c + x1 * s;
}

// ---------------- scores via HMMA: S = (q.k)/sqrt(HD), lower-tri tiles ----------------
__global__ __launch_bounds__(256) void scores_mma() {
    const int bh = blockIdx.z;
    const int b = bh >> 5, h = bh & 31;
    const int kvh = h >> 2;
    const int m0 = blockIdx.y * 128;
    const int n0 = blockIdx.x * 128;
    if (n0 > m0) return;

    const float* __restrict__ A  = g_q + (size_t)b * Ss * QD  + (size_t)h * HDd;
    const float* __restrict__ Bk = g_k + (size_t)b * Ss * KVD + (size_t)kvh * HDd;
    float* __restrict__ C = g_scores + (size_t)bh * Ss * Ss;

    __shared__ __align__(16) __nv_bfloat16 sqh[128 * ST];
    __shared__ __align__(16) __nv_bfloat16 sql[128 * ST];
    __shared__ __align__(16) __nv_bfloat16 skh[128 * ST];
    __shared__ __align__(16) __nv_bfloat16 skl[128 * ST];

    const int tid  = threadIdx.x;
    const int wid  = tid >> 5;
    const int lane = tid & 31;
    const int g    = lane >> 2;
    const int t    = lane & 3;
    const int wrow = (wid >> 2) * 64;
    const int wcol = (wid & 3) * 32;

    float acc[4][4][4];
#pragma unroll
    for (int i = 0; i < 4; i++)
#pragma unroll
        for (int j = 0; j < 4; j++)
#pragma unroll
            for (int r = 0; r < 4; r++) acc[i][j][r] = 0.f;

    for (int kc = 0; kc < HDd; kc += 32) {
#pragma unroll
        for (int l = 0; l < 4; l++) {
            int seg = tid + l * 256;
            int row = seg >> 3;
            int c4  = (seg & 7) * 4;
            float4 va = *(const float4*)&A[(size_t)(m0 + row) * QD + kc + c4];
            float hx = __bfloat162float(__float2bfloat16_rn(va.x));
            float hy = __bfloat162float(__float2bfloat16_rn(va.y));
            float hz = __bfloat162float(__float2bfloat16_rn(va.z));
            float hw = __bfloat162float(__float2bfloat16_rn(va.w));
            *(uint32_t*)&sqh[row * ST + c4]     = packbf(hx, hy);
            *(uint32_t*)&sqh[row * ST + c4 + 2] = packbf(hz, hw);
            *(uint32_t*)&sql[row * ST + c4]     = packbf(va.x - hx, va.y - hy);
            *(uint32_t*)&sql[row * ST + c4 + 2] = packbf(va.z - hz, va.w - hw);

            float4 vb = *(const float4*)&Bk[(size_t)(n0 + row) * KVD + kc + c4];
            float gx = __bfloat162float(__float2bfloat16_rn(vb.x));
            float gy = __bfloat162float(__float2bfloat16_rn(vb.y));
            float gz = __bfloat162float(__float2bfloat16_rn(vb.z));
            float gw = __bfloat162float(__float2bfloat16_rn(vb.w));
            *(uint32_t*)&skh[row * ST + c4]     = packbf(gx, gy);
            *(uint32_t*)&skh[row * ST + c4 + 2] = packbf(gz, gw);
            *(uint32_t*)&skl[row * ST + c4]     = packbf(vb.x - gx, vb.y - gy);
            *(uint32_t*)&skl[row * ST + c4 + 2] = packbf(vb.z - gz, vb.w - gw);
        }
        __syncthreads();

#pragma unroll
        for (int kk = 0; kk < 32; kk += 16) {
            uint32_t ah[4][4], al[4][4], bh2[4][2], bl2[4][2];
#pragma unroll
            for (int mt = 0; mt < 4; mt++) {
                int m = wrow + mt * 16 + g;
                ah[mt][0] = *(const uint32_t*)&sqh[(m    ) * ST + kk + 2 * t    ];
                ah[mt][1] = *(const uint32_t*)&sqh[(m + 8) * ST + kk + 2 * t    ];
                ah[mt][2] = *(const uint32_t*)&sqh[(m    ) * ST + kk + 2 * t + 8];
                ah[mt][3] = *(const uint32_t*)&sqh[(m + 8) * ST + kk + 2 * t + 8];
                al[mt][0] = *(const uint32_t*)&sql[(m    ) * ST + kk + 2 * t    ];
                al[mt][1] = *(const uint32_t*)&sql[(m + 8) * ST + kk + 2 * t    ];
                al[mt][2] = *(const uint32_t*)&sql[(m    ) * ST + kk + 2 * t + 8];
                al[mt][3] = *(const uint32_t*)&sql[(m + 8) * ST + kk + 2 * t + 8];
            }
#pragma unroll
            for (int nt = 0; nt < 4; nt++) {
                int n = wcol + nt * 8 + g;
                bh2[nt][0] = *(const uint32_t*)&skh[n * ST + kk + 2 * t    ];
                bh2[nt][1] = *(const uint32_t*)&skh[n * ST + kk + 2 * t + 8];
                bl2[nt][0] = *(const uint32_t*)&skl[n * ST + kk + 2 * t    ];
                bl2[nt][1] = *(const uint32_t*)&skl[n * ST + kk + 2 * t + 8];
            }
#pragma unroll
            for (int mt = 0; mt < 4; mt++)
#pragma unroll
                for (int nt = 0; nt < 4; nt++) {
                    mma16816(acc[mt][nt], ah[mt], bh2[nt]);
                    mma16816(acc[mt][nt], al[mt], bh2[nt]);
                    mma16816(acc[mt][nt], ah[mt], bl2[nt]);
                }
        }
        __syncthreads();
    }

    const float scale = 0.08838834764831845f;
#pragma unroll
    for (int mt = 0; mt < 4; mt++) {
#pragma unroll
        for (int nt = 0; nt < 4; nt++) {
            int m = m0 + wrow + mt * 16 + g;
            int n = n0 + wcol + nt * 8 + 2 * t;
            if (n     <= m) C[(size_t)m * Ss + n]     = acc[mt][nt][0] * scale;
            if (n + 1 <= m) C[(size_t)m * Ss + n + 1] = acc[mt][nt][1] * scale;
            int m8 = m + 8;
            if (n     <= m8) C[(size_t)m8 * Ss + n]     = acc[mt][nt][2] * scale;
            if (n + 1 <= m8) C[(size_t)m8 * Ss + n + 1] = acc[mt][nt][3] * scale;
        }
    }
}

// ---------------- rowstat: per-row (max, 1/sum(exp)) over j<=i ----------------
__global__ void rowstat_kernel() {
    const int row = blockIdx.x;
    const int i = row & (Ss - 1);
    const float* __restrict__ p = g_scores + (size_t)row * Ss;
    __shared__ float buf[Ss];
    __shared__ float red[40];
    const int len = i + 1;

    float mx = -INFINITY;
    for (int j = threadIdx.x; j < len; j += blockDim.x) {
        float v = p[j]; buf[j] = v; mx = fmaxf(mx, v);
    }
#pragma unroll
    for (int o = 16; o; o >>= 1) mx = fmaxf(mx, __shfl_xor_sync(0xffffffffu, mx, o));
    if ((threadIdx.x & 31) == 0) red[threadIdx.x >> 5] = mx;
    __syncthreads();
    if (threadIdx.x == 0) {
        float m = red[0];
        for (int w = 1; w < 8; w++) m = fmaxf(m, red[w]);
        red[32] = m;
    }
    __syncthreads();
    mx = red[32];

    float sum = 0.f;
    for (int j = threadIdx.x; j < len; j += blockDim.x)
        sum += expf(buf[j] - mx);
#pragma unroll
    for (int o = 16; o; o >>= 1) sum += __shfl_xor_sync(0xffffffffu, sum, o);
    __syncthreads();
    if ((threadIdx.x & 31) == 0) red[threadIdx.x >> 5] = sum;
    __syncthreads();
    if (threadIdx.x == 0) {
        float s = red[0];
        for (int w = 1; w < 8; w++) s += red[w];
        g_rowstat[row] = make_float2(mx, 1.f / s);
    }
}

// ---------------- PV via HMMA; softmax on the fly; writes int8 digit planes ----------------
__global__ __launch_bounds__(256) void pv_mma() {
    const int bh = blockIdx.y;
    const int b = bh >> 5, h = bh & 31;
    const int kvh = h >> 2;
    const int bk = b * NKVh + kvh;
    const int m0 = blockIdx.x * 128;

    const float* __restrict__ A = g_scores + (size_t)bh * Ss * Ss;
    const float2* __restrict__ RS = g_rowstat + (size_t)bh * Ss;
    const __nv_bfloat16* __restrict__ Vh = g_vhi + (size_t)bk * HDd * Ss;
    const __nv_bfloat16* __restrict__ Vl = g_vlo + (size_t)bk * HDd * Ss;
    int8_t* __restrict__ O0 = g_a0 + (size_t)b * Ss * QD + (size_t)h * HDd;
    int8_t* __restrict__ O1 = g_a1 + (size_t)b * Ss * QD + (size_t)h * HDd;

    __shared__ __align__(16) __nv_bfloat16 sph[128 * ST];
    __shared__ __align__(16) __nv_bfloat16 spl[128 * ST];
    __shared__ __align__(16) __nv_bfloat16 svh[128 * ST];
    __shared__ __align__(16) __nv_bfloat16 svl[128 * ST];

    const int tid  = threadIdx.x;
    const int wid  = tid >> 5;
    const int lane = tid & 31;
    const int g    = lane >> 2;
    const int t    = lane & 3;
    const int wrow = (wid >> 2) * 64;
    const int wcol = (wid & 3) * 32;

    float acc[4][4][4];
#pragma unroll
    for (int i = 0; i < 4; i++)
#pragma unroll
        for (int j = 0; j < 4; j++)
#pragma unroll
            for (int r = 0; r < 4; r++) acc[i][j][r] = 0.f;

    const int kmax = m0 + 128;
    for (int kc = 0; kc < kmax; kc += 32) {
#pragma unroll
        for (int l = 0; l < 4; l++) {
            int seg = tid + l * 256;
            int row = seg >> 3;
            int c4  = (seg & 7) * 4;
            int mrow = m0 + row;
            float2 st = RS[mrow];
            float4 va = *(const float4*)&A[(size_t)mrow * Ss + kc + c4];
            int col = kc + c4;
            float px = (col     <= mrow) ? expf(va.x - st.x) * st.y : 0.f;
            float py = (col + 1 <= mrow) ? expf(va.y - st.x) * st.y : 0.f;
            float pz = (col + 2 <= mrow) ? expf(va.z - st.x) * st.y : 0.f;
            float pw = (col + 3 <= mrow) ? expf(va.w - st.x) * st.y : 0.f;
            float hx = __bfloat162float(__float2bfloat16_rn(px));
            float hy = __bfloat162float(__float2bfloat16_rn(py));
            float hz = __bfloat162float(__float2bfloat16_rn(pz));
            float hw = __bfloat162float(__float2bfloat16_rn(pw));
            *(uint32_t*)&sph[row * ST + c4]     = packbf(hx, hy);
            *(uint32_t*)&sph[row * ST + c4 + 2] = packbf(hz, hw);
            *(uint32_t*)&spl[row * ST + c4]     = packbf(px - hx, py - hy);
            *(uint32_t*)&spl[row * ST + c4 + 2] = packbf(pz - hz, pw - hw);
        }
#pragma unroll
        for (int l = 0; l < 2; l++) {
            int seg = tid + l * 256;
            int row = seg >> 2;
            int cs  = (seg & 3) * 8;
            *(uint4*)&svh[row * ST + cs] = *(const uint4*)&Vh[(size_t)row * Ss + kc + cs];
            *(uint4*)&svl[row * ST + cs] = *(const uint4*)&Vl[(size_t)row * Ss + kc + cs];
        }
        __syncthreads();

#pragma unroll
        for (int kk = 0; kk < 32; kk += 16) {
            uint32_t ah[4][4], al[4][4], bh2[4][2], bl2[4][2];
#pragma unroll
            for (int mt = 0; mt < 4; mt++) {
                int m = wrow + mt * 16 + g;
                ah[mt][0] = *(const uint32_t*)&sph[(m    ) * ST + kk + 2 * t    ];
                ah[mt][1] = *(const uint32_t*)&sph[(m + 8) * ST + kk + 2 * t    ];
                ah[mt][2] = *(const uint32_t*)&sph[(m    ) * ST + kk + 2 * t + 8];
                ah[mt][3] = *(const uint32_t*)&sph[(m + 8) * ST + kk + 2 * t + 8];
                al[mt][0] = *(const uint32_t*)&spl[(m    ) * ST + kk + 2 * t    ];
                al[mt][1] = *(const uint32_t*)&spl[(m + 8) * ST + kk + 2 * t    ];
                al[mt][2] = *(const uint32_t*)&spl[(m    ) * ST + kk + 2 * t + 8];
                al[mt][3] = *(const uint32_t*)&spl[(m + 8) * ST + kk + 2 * t + 8];
            }
#pragma unroll
            for (int nt = 0; nt < 4; nt++) {
                int n = wcol + nt * 8 + g;
                bh2[nt][0] = *(const uint32_t*)&svh[n * ST + kk + 2 * t    ];
                bh2[nt][1] = *(const uint32_t*)&svh[n * ST + kk + 2 * t + 8];
                bl2[nt][0] = *(const uint32_t*)&svl[n * ST + kk + 2 * t    ];
                bl2[nt][1] = *(const uint32_t*)&svl[n * ST + kk + 2 * t + 8];
            }
#pragma unroll
            for (int mt = 0; mt < 4; mt++)
#pragma unroll
                for (int nt = 0; nt < 4; nt++) {
                    mma16816(acc[mt][nt], ah[mt], bh2[nt]);
                    mma16816(acc[mt][nt], al[mt], bh2[nt]);
                    mma16816(acc[mt][nt], ah[mt], bl2[nt]);
                }
        }
        __syncthreads();
    }

#pragma unroll
    for (int mt = 0; mt < 4; mt++) {
#pragma unroll
        for (int nt = 0; nt < 4; nt++) {
            int m = m0 + wrow + mt * 16 + g;
            int n = wcol + nt * 8 + 2 * t;
            int x0, x1, y0, y1;
            qdigits(acc[mt][nt][0], x0, x1);
            qdigits(acc[mt][nt][1], y0, y1);
            *(short*)&O0[(size_t)m * QD + n] = (short)(((y0 & 0xFF) << 8) | (x0 & 0xFF));
            *(short*)&O1[(size_t)m * QD + n] = (short)(((y1 & 0xFF) << 8) | (x1 & 0xFF));
            qdigits(acc[mt][nt][2], x0, x1);
            qdigits(acc[mt][nt][3], y0, y1);
            *(short*)&O0[(size_t)(m + 8) * QD + n] = (short)(((y0 & 0xFF) << 8) | (x0 & 0xFF));
            *(short*)&O1[(size_t)(m + 8) * QD + n] = (short)(((y1 & 0xFF) << 8) | (x1 & 0xFF));
        }
    }
}

// ---------------- launch ----------------
extern "C" void kernel_launch(void* const* d_in, const int* in_sizes, int n_in,
                              void* d_out, int out_size)
{
    const float* hidden = nullptr;
    const float* big16[2] = {nullptr, nullptr};
    const float* sml4[2]  = {nullptr, nullptr};
    const int*   posid = nullptr;
    int hidden_idx = -1, nb = 0, ns = 0;
    for (int i = 0; i < n_in; i++) {
        if (in_sizes[i] == 8388608)               { hidden = (const float*)d_in[i]; hidden_idx = i; }
        else if (in_sizes[i] == 16777216 && nb<2) { big16[nb++] = (const float*)d_in[i]; }
        else if (in_sizes[i] == 4194304  && ns<2) { sml4[ns++]  = (const float*)d_in[i]; }
        else if (in_sizes[i] == 2048)             { posid = (const int*)d_in[i]; }
    }
    const float* Wq = (hidden_idx == 0) ? big16[0] : big16[1];
    const float* Wo = (hidden_idx == 0) ? big16[1] : big16[0];
    const float* Wk = sml4[0];
    const float* Wv = sml4[1];
    float* out = (float*)d_out;

    void *pq, *pk, *pv, *pa0, *pa1, *pwq, *pwk, *pwv, *pwo;
    cudaGetSymbolAddress(&pq, g_q);
    cudaGetSymbolAddress(&pk, g_k);
    cudaGetSymbolAddress(&pv, g_v);
    cudaGetSymbolAddress(&pa0, g_a0);
    cudaGetSymbolAddress(&pa1, g_a1);
    cudaGetSymbolAddress(&pwq, g_wq);
    cudaGetSymbolAddress(&pwk, g_wk);
    cudaGetSymbolAddress(&pwv, g_wv);
    cudaGetSymbolAddress(&pwo, g_wo);

    cudaFuncSetAttribute(gemm_imma, cudaFuncAttributeMaxDynamicSharedMemorySize, GI_SMEM);

    const size_t nQ4 = (size_t)QD * Hh / 4;
    const size_t nK4 = (size_t)KVD * Hh / 4;
    const size_t nO4 = (size_t)Hh * QD / 4;
    const size_t nH4 = (size_t)MTOK * Hh / 4;

    cudaStream_t s2;
    cudaEvent_t ev0, evK, evV, evO, evVg, evVS;
    cudaStreamCreateWithFlags(&s2, cudaStreamNonBlocking);
    cudaEventCreateWithFlags(&ev0, cudaEventDisableTiming);
    cudaEventCreateWithFlags(&evK, cudaEventDisableTiming);
    cudaEventCreateWithFlags(&evV, cudaEventDisableTiming);
    cudaEventCreateWithFlags(&evO, cudaEventDisableTiming);
    cudaEventCreateWithFlags(&evVg, cudaEventDisableTiming);
    cudaEventCreateWithFlags(&evVS, cudaEventDisableTiming);

    init_kernel<<<1, 32>>>();
    cudaEventRecord(ev0, 0);
    cudaStreamWaitEvent(s2, ev0, 0);

    // side stream: K/V/O weight preprocessing
    abssum_kernel<<<2048, 256, 0, s2>>>((const float4*)Wk, nK4, 1);
    quantize_w<<<4096, 256, 0, s2>>>((const float4*)Wk, (char4*)pwk, nK4, 1);
    cudaEventRecord(evK, s2);
    abssum_kernel<<<2048, 256, 0, s2>>>((const float4*)Wv, nK4, 2);
    quantize_w<<<4096, 256, 0, s2>>>((const float4*)Wv, (char4*)pwv, nK4, 2);
    cudaEventRecord(evV, s2);
    abssum_kernel<<<2048, 256, 0, s2>>>((const float4*)Wo, nO4, 3);
    quantize_w<<<4096, 256, 0, s2>>>((const float4*)Wo, (char4*)pwo, nO4, 3);
    cudaEventRecord(evO, s2);

    // main stream: Q path
    abssum_kernel<<<2048, 256>>>((const float4*)Wq, nQ4, 0);
    quantize_w<<<4096, 256>>>((const float4*)Wq, (char4*)pwq, nQ4, 0);
    aquant_kernel<<<4096, 256>>>((const float4*)hidden, (char4*)pa0, (char4*)pa1, nH4);
    gemm_imma<<<dim3(QD / 128, MTOK / 128), 256, GI_SMEM>>>(
        (const int8_t*)pa0, (const int8_t*)pa1, (const int8_t*)pwq,
        (float*)pq, QD, Hh, 0);

    cudaStreamWaitEvent(0, evK, 0);
    gemm_imma<<<dim3(KVD / 128, MTOK / 128), 256, GI_SMEM>>>(
        (const int8_t*)pa0, (const int8_t*)pa1, (const int8_t*)pwk,
        (float*)pk, KVD, Hh, 1);
    cudaStreamWaitEvent(0, evV, 0);
    gemm_imma<<<dim3(KVD / 128, MTOK / 128), 256, GI_SMEM>>>(
        (const int8_t*)pa0, (const int8_t*)pa1, (const int8_t*)pwv,
        (float*)pv, KVD, Hh, 2);
    cudaEventRecord(evVg, 0);

    // side stream: V transpose/split overlaps rope/scores
    cudaStreamWaitEvent(s2, evVg, 0);
    vsplit_kernel<<<(int)(((size_t)Bb * NKVh * HDd * Ss + 255) / 256), 256, 0, s2>>>();
    cudaEventRecord(evVS, s2);

    rope_kernel<<<(int)(((size_t)MTOK * NHq * 64 + 255) / 256), 256>>>((float*)pq, NHq, posid);
    rope_kernel<<<(int)(((size_t)MTOK * NKVh * 64 + 255) / 256), 256>>>((float*)pk, NKVh, posid);

    scores_mma<<<dim3(8, 8, Bb * NHq), 256>>>();
    rowstat_kernel<<<Bb * NHq * Ss, 256>>>();
    cudaStreamWaitEvent(0, evVS, 0);
    pv_mma<<<dim3(8, Bb * NHq), 256>>>();

    cudaStreamWaitEvent(0, evO, 0);
    gemm_imma<<<dim3(Hh / 128, MTOK / 128), 256, GI_SMEM>>>(
        (const int8_t*)pa0, (const int8_t*)pa1, (const int8_t*)pwo,
        out, Hh, QD, 3);
}

// round 13
// speedup vs baseline: 2.0143x; 2.0143x over previous
#include <cuda_runtime.h>
#include <cuda_bf16.h>
#include <math.h>
#include <stdint.h>

// Problem constants
constexpr int Bb   = 2;
constexpr int Ss   = 1024;
constexpr int Hh   = 4096;
constexpr int NHq  = 32;
constexpr int NKVh = 8;
constexpr int HDd  = 128;
constexpr int MTOK = Bb * Ss;             // 2048
constexpr int QD   = NHq * HDd;           // 4096
constexpr int KVD  = NKVh * HDd;          // 1024

// ---------------- device scratch (static; allocation-free) ----------------
__device__ float          g_q[(size_t)MTOK * QD];
__device__ float          g_k[(size_t)MTOK * KVD];
__device__ float          g_v[(size_t)MTOK * KVD];
__device__ __nv_bfloat16  g_ahi[(size_t)MTOK * Hh];
__device__ __nv_bfloat16  g_alo[(size_t)MTOK * Hh];
__device__ __nv_bfloat16  g_wq[(size_t)QD  * Hh];
__device__ __nv_bfloat16  g_wk[(size_t)KVD * Hh];
__device__ __nv_bfloat16  g_wv[(size_t)KVD * Hh];
__device__ __nv_bfloat16  g_wo[(size_t)Hh  * QD];
__device__ __nv_bfloat16  g_vhi[(size_t)Bb * NKVh * HDd * Ss];
__device__ __nv_bfloat16  g_vlo[(size_t)Bb * NKVh * HDd * Ss];
__device__ double         g_absum[4];
__device__ float          g_gamma[4];

// ---------------- helpers ----------------
__device__ __forceinline__ uint32_t smem_u32(const void* p) {
    uint32_t a;
    asm("{ .reg .u64 t; cvta.to.shared.u64 t, %1; cvt.u32.u64 %0, t; }" : "=r"(a) : "l"(p));
    return a;
}
__device__ __forceinline__ uint32_t packbf(float a, float b) {
    __nv_bfloat162 t = __floats2bfloat162_rn(a, b);
    return *(uint32_t*)&t;
}
__device__ __forceinline__ void mma16816(float* c, const uint32_t* a, const uint32_t* b) {
    asm volatile(
        "mma.sync.aligned.m16n8k16.row.col.f32.bf16.bf16.f32 "
        "{%0,%1,%2,%3}, {%4,%5,%6,%7}, {%8,%9}, {%0,%1,%2,%3};"
        : "+f"(c[0]), "+f"(c[1]), "+f"(c[2]), "+f"(c[3])
        : "r"(a[0]), "r"(a[1]), "r"(a[2]), "r"(a[3]), "r"(b[0]), "r"(b[1]));
}
#define CP_ASYNC16(dst, src) \
    asm volatile("cp.async.cg.shared.global [%0], [%1], 16;" :: "r"(dst), "l"(src))
#define CP_COMMIT() asm volatile("cp.async.commit_group;" ::: "memory")
#define CP_WAIT1()  asm volatile("cp.async.wait_group 1;" ::: "memory")
#define CP_WAIT0()  asm volatile("cp.async.wait_group 0;" ::: "memory")

constexpr int ST = 40;   // bf16 smem row stride for 32-wide k-chunks

// ---------------- gamma: abs-sum reduction (float4) ----------------
__global__ void init_kernel() {
    if (threadIdx.x < 4) g_absum[threadIdx.x] = 0.0;
}

__global__ void abssum_kernel(const float4* __restrict__ w, size_t n4, int idx) {
    float s = 0.f;
    for (size_t i = (size_t)blockIdx.x * blockDim.x + threadIdx.x; i < n4;
         i += (size_t)gridDim.x * blockDim.x) {
        float4 v = w[i];
        s += fabsf(v.x) + fabsf(v.y) + fabsf(v.z) + fabsf(v.w);
    }
    __shared__ double sh[256];
    sh[threadIdx.x] = (double)s;
    __syncthreads();
    for (int o = 128; o > 0; o >>= 1) {
        if ((int)threadIdx.x < o) sh[threadIdx.x] += sh[threadIdx.x + o];
        __syncthreads();
    }
    if (threadIdx.x == 0) atomicAdd(&g_absum[idx], sh[0]);
}

// ---------------- ternary quantization -> bf16 plane ----------------
__global__ void quantize_kernel(const float4* __restrict__ w,
                                __nv_bfloat162* __restrict__ t, size_t n4, int idx) {
    float gamma = (float)(g_absum[idx] / (double)(n4 * 4)) + 1e-5f;
    if (blockIdx.x == 0 && threadIdx.x == 0) g_gamma[idx] = gamma;
    for (size_t i = (size_t)blockIdx.x * blockDim.x + threadIdx.x; i < n4;
         i += (size_t)gridDim.x * blockDim.x) {
        float4 v = w[i];
        float rx = fminf(1.f, fmaxf(-1.f, rintf(v.x / gamma)));
        float ry = fminf(1.f, fmaxf(-1.f, rintf(v.y / gamma)));
        float rz = fminf(1.f, fmaxf(-1.f, rintf(v.z / gamma)));
        float rw = fminf(1.f, fmaxf(-1.f, rintf(v.w / gamma)));
        t[2 * i]     = __floats2bfloat162_rn(rx, ry);
        t[2 * i + 1] = __floats2bfloat162_rn(rz, rw);
    }
}

// ---------------- fp32 -> (hi,lo) bf16 planes ----------------
__global__ void split2_kernel(const float4* __restrict__ x,
                              __nv_bfloat162* __restrict__ hi,
                              __nv_bfloat162* __restrict__ lo, size_t n4) {
    for (size_t i = (size_t)blockIdx.x * blockDim.x + threadIdx.x; i < n4;
         i += (size_t)gridDim.x * blockDim.x) {
        float4 f = x[i];
        __nv_bfloat162 hxy = __floats2bfloat162_rn(f.x, f.y);
        __nv_bfloat162 hzw = __floats2bfloat162_rn(f.z, f.w);
        hi[2 * i]     = hxy;
        hi[2 * i + 1] = hzw;
        lo[2 * i]     = __floats2bfloat162_rn(f.x - __bfloat162float(hxy.x),
                                              f.y - __bfloat162float(hxy.y));
        lo[2 * i + 1] = __floats2bfloat162_rn(f.z - __bfloat162float(hzw.x),
                                              f.w - __bfloat162float(hzw.y));
    }
}

// ---------------- V -> transposed hi/lo planes: vt[bk][d][s] ----------------
__global__ void vsplit_kernel() {
    size_t idx = (size_t)blockIdx.x * blockDim.x + threadIdx.x;
    if (idx >= (size_t)Bb * NKVh * HDd * Ss) return;
    int s  = (int)(idx & (Ss - 1));
    int d  = (int)((idx >> 10) & 127);
    int bk = (int)(idx >> 17);
    int b  = bk >> 3, kv = bk & 7;
    float v = g_v[((size_t)(b * Ss + s)) * KVD + kv * HDd + d];
    __nv_bfloat16 h = __float2bfloat16_rn(v);
    g_vhi[idx] = h;
    g_vlo[idx] = __float2bfloat16_rn(v - __bfloat162float(h));
}

// ================= cp.async-pipelined projection GEMM (128x128 tile, 2-stage) =================
constexpr int PLANE   = 128 * ST;
constexpr int GM_SMEM = 2 * 3 * PLANE * 2;        // 61440 B

__global__ __launch_bounds__(256) void gemm_mma2(
    const __nv_bfloat16* __restrict__ Ahi, const __nv_bfloat16* __restrict__ Alo,
    const __nv_bfloat16* __restrict__ W, float* __restrict__ C,
    int N, int K, int gidx)
{
    extern __shared__ __align__(16) __nv_bfloat16 sb[];
    const uint32_t ubase = smem_u32(sb);

    const int tid  = threadIdx.x;
    const int wid  = tid >> 5;
    const int lane = tid & 31;
    const int g    = lane >> 2;
    const int t    = lane & 3;
    const int m0   = blockIdx.y * 128;
    const int n0   = blockIdx.x * 128;
    const int wrow = (wid >> 2) * 64;
    const int wcol = (wid & 3) * 32;

    const int r0 = (tid * 2)     >> 2, c0 = ((tid * 2)     & 3) * 8;
    const int r1 = (tid * 2 + 1) >> 2, c1 = ((tid * 2 + 1) & 3) * 8;

    float acc[4][4][4];
#pragma unroll
    for (int i = 0; i < 4; i++)
#pragma unroll
        for (int j = 0; j < 4; j++)
#pragma unroll
            for (int r = 0; r < 4; r++) acc[i][j][r] = 0.f;

    const int iters = K >> 5;

    auto issue = [&](int it, int stg) {
        const int kc = it << 5;
        uint32_t s0 = ubase + (uint32_t)(stg * 3 * PLANE) * 2;
        CP_ASYNC16(s0 + (r0 * ST + c0) * 2,               &Ahi[(size_t)(m0 + r0) * K + kc + c0]);
        CP_ASYNC16(s0 + (r1 * ST + c1) * 2,               &Ahi[(size_t)(m0 + r1) * K + kc + c1]);
        CP_ASYNC16(s0 + (PLANE + r0 * ST + c0) * 2,       &Alo[(size_t)(m0 + r0) * K + kc + c0]);
        CP_ASYNC16(s0 + (PLANE + r1 * ST + c1) * 2,       &Alo[(size_t)(m0 + r1) * K + kc + c1]);
        CP_ASYNC16(s0 + (2 * PLANE + r0 * ST + c0) * 2,   &W[(size_t)(n0 + r0) * K + kc + c0]);
        CP_ASYNC16(s0 + (2 * PLANE + r1 * ST + c1) * 2,   &W[(size_t)(n0 + r1) * K + kc + c1]);
        CP_COMMIT();
    };

    issue(0, 0);
    for (int it = 0; it < iters; ++it) {
        const int stg = it & 1;
        if (it + 1 < iters) { issue(it + 1, stg ^ 1); CP_WAIT1(); }
        else                { CP_WAIT0(); }
        __syncthreads();

        const __nv_bfloat16* sah = sb + stg * 3 * PLANE;
        const __nv_bfloat16* sal = sah + PLANE;
        const __nv_bfloat16* sbw = sah + 2 * PLANE;

#pragma unroll
        for (int kk = 0; kk < 32; kk += 16) {
            uint32_t ah[4][4], al[4][4], bf[4][2];
#pragma unroll
            for (int mt = 0; mt < 4; mt++) {
                int m = wrow + mt * 16 + g;
                ah[mt][0] = *(const uint32_t*)&sah[(m    ) * ST + kk + 2 * t    ];
                ah[mt][1] = *(const uint32_t*)&sah[(m + 8) * ST + kk + 2 * t    ];
                ah[mt][2] = *(const uint32_t*)&sah[(m    ) * ST + kk + 2 * t + 8];
                ah[mt][3] = *(const uint32_t*)&sah[(m + 8) * ST + kk + 2 * t + 8];
                al[mt][0] = *(const uint32_t*)&sal[(m    ) * ST + kk + 2 * t    ];
                al[mt][1] = *(const uint32_t*)&sal[(m + 8) * ST + kk + 2 * t    ];
                al[mt][2] = *(const uint32_t*)&sal[(m    ) * ST + kk + 2 * t + 8];
                al[mt][3] = *(const uint32_t*)&sal[(m + 8) * ST + kk + 2 * t + 8];
            }
#pragma unroll
            for (int nt = 0; nt < 4; nt++) {
                int n = wcol + nt * 8 + g;
                bf[nt][0] = *(const uint32_t*)&sbw[n * ST + kk + 2 * t    ];
                bf[nt][1] = *(const uint32_t*)&sbw[n * ST + kk + 2 * t + 8];
            }
#pragma unroll
            for (int mt = 0; mt < 4; mt++)
#pragma unroll
                for (int nt = 0; nt < 4; nt++) {
                    mma16816(acc[mt][nt], ah[mt], bf[nt]);
                    mma16816(acc[mt][nt], al[mt], bf[nt]);
                }
        }
        __syncthreads();
    }

    const float gamma = g_gamma[gidx];
#pragma unroll
    for (int mt = 0; mt < 4; mt++) {
#pragma unroll
        for (int nt = 0; nt < 4; nt++) {
            int m = m0 + wrow + mt * 16 + g;
            int n = n0 + wcol + nt * 8 + 2 * t;
            float2 lo = make_float2(acc[mt][nt][0] * gamma, acc[mt][nt][1] * gamma);
            float2 hi = make_float2(acc[mt][nt][2] * gamma, acc[mt][nt][3] * gamma);
            *(float2*)&C[(size_t)m * N + n]       = lo;
            *(float2*)&C[(size_t)(m + 8) * N + n] = hi;
        }
    }
}

// ---------------- RoPE (in place), uses position_ids ----------------
__global__ void rope_kernel(float* __restrict__ x, int nheads,
                            const int* __restrict__ pos_ids) {
    size_t idx = (size_t)blockIdx.x * blockDim.x + threadIdx.x;
    size_t total = (size_t)MTOK * nheads * 64;
    if (idx >= total) return;
    int d = (int)(idx & 63);
    size_t th = idx >> 6;
    int head = (int)(th % nheads);
    size_t tok = th / nheads;
    int pos = pos_ids[tok];
    float inv_freq = 1.0f / powf(10000.0f, (float)d * (1.0f / 64.0f));
    float fr = (float)pos * inv_freq;
    float s, c;
    sincosf(fr, &s, &c);
    float* base = x + tok * ((size_t)nheads * HDd) + (size_t)head * HDd;
    float x1 = base[d], x2 = base[d + 64];
    base[d]      = x1 * c - x2 * s;
    base[d + 64] = x2 * c + x1 * s;
}

// ================= fused flash attention =================
// One kernel: S = QK^T/sqrt(HD) (causal), online softmax, O = P V.
// Block: 128 Q-rows; loops over causal K-tiles of 128. Writes O as hi/lo bf16 planes.
// smem layout (bytes):
//   [0      : 10240)  sqh   (128 x ST bf16)
//   [10240  : 20480)  sql
//   [20480  : 30720)  skh
//   [30720  : 40960)  skl
//   [40960  : 43008)  red   (128 x 4 float)
//   [43008  : 77824)  Ph    (128 x 136 bf16)
//   [77824  : 112640) Pl
//   [112640 : 147456) Svh   (V^T hi, 128 x 136 bf16)
//   [147456 : 182272) Svl
constexpr int PST = 136;
constexpr int FL_SMEM = 182272;

__global__ __launch_bounds__(256) void flash_mma() {
    extern __shared__ char ds[];
    __nv_bfloat16* sqh = (__nv_bfloat16*)(ds);
    __nv_bfloat16* sql = (__nv_bfloat16*)(ds + 10240);
    __nv_bfloat16* skh = (__nv_bfloat16*)(ds + 20480);
    __nv_bfloat16* skl = (__nv_bfloat16*)(ds + 30720);
    float*         red = (float*)        (ds + 40960);
    __nv_bfloat16* Ph  = (__nv_bfloat16*)(ds + 43008);
    __nv_bfloat16* Pl  = (__nv_bfloat16*)(ds + 77824);
    __nv_bfloat16* Svh = (__nv_bfloat16*)(ds + 112640);
    __nv_bfloat16* Svl = (__nv_bfloat16*)(ds + 147456);

    const int bh = blockIdx.y;
    const int b = bh >> 5, h = bh & 31;
    const int kvh = h >> 2;
    const int bk = b * NKVh + kvh;
    const int m0 = blockIdx.x * 128;

    const float* __restrict__ Q  = g_q + (size_t)b * Ss * QD  + (size_t)h * HDd;
    const float* __restrict__ Kp = g_k + (size_t)b * Ss * KVD + (size_t)kvh * HDd;
    const __nv_bfloat16* __restrict__ Vh = g_vhi + (size_t)bk * HDd * Ss;
    const __nv_bfloat16* __restrict__ Vl = g_vlo + (size_t)bk * HDd * Ss;
    __nv_bfloat16* __restrict__ Ohi = g_ahi + (size_t)b * Ss * QD + (size_t)h * HDd;
    __nv_bfloat16* __restrict__ Olo = g_alo + (size_t)b * Ss * QD + (size_t)h * HDd;

    const int tid  = threadIdx.x;
    const int wid  = tid >> 5;
    const int lane = tid & 31;
    const int g    = lane >> 2;
    const int t    = lane & 3;
    const int wrow = (wid >> 2) * 64;
    const int wcol = (wid & 3) * 32;
    const int wc   = wid & 3;
    const float scale = 0.08838834764831845f;  // 1/sqrt(128)

    float oacc[4][4][4];
    float M[8], L[8];
#pragma unroll
    for (int i = 0; i < 4; i++)
#pragma unroll
        for (int j = 0; j < 4; j++)
#pragma unroll
            for (int r = 0; r < 4; r++) oacc[i][j][r] = 0.f;
#pragma unroll
    for (int i = 0; i < 8; i++) { M[i] = -INFINITY; L[i] = 0.f; }

    for (int n0 = 0; n0 <= m0; n0 += 128) {
        // ---------- QK: s = Q . K^T ----------
        float s[4][4][4];
#pragma unroll
        for (int i = 0; i < 4; i++)
#pragma unroll
            for (int j = 0; j < 4; j++)
#pragma unroll
                for (int r = 0; r < 4; r++) s[i][j][r] = 0.f;

        for (int kc = 0; kc < HDd; kc += 32) {
#pragma unroll
            for (int l = 0; l < 4; l++) {
                int seg = tid + l * 256;
                int row = seg >> 3;
                int c4  = (seg & 7) * 4;
                float4 va = *(const float4*)&Q[(size_t)(m0 + row) * QD + kc + c4];
                float hx = __bfloat162float(__float2bfloat16_rn(va.x));
                float hy = __bfloat162float(__float2bfloat16_rn(va.y));
                float hz = __bfloat162float(__float2bfloat16_rn(va.z));
                float hw = __bfloat162float(__float2bfloat16_rn(va.w));
                *(uint32_t*)&sqh[row * ST + c4]     = packbf(hx, hy);
                *(uint32_t*)&sqh[row * ST + c4 + 2] = packbf(hz, hw);
                *(uint32_t*)&sql[row * ST + c4]     = packbf(va.x - hx, va.y - hy);
                *(uint32_t*)&sql[row * ST + c4 + 2] = packbf(va.z - hz, va.w - hw);

                float4 vb = *(const float4*)&Kp[(size_t)(n0 + row) * KVD + kc + c4];
                float gx = __bfloat162float(__float2bfloat16_rn(vb.x));
                float gy = __bfloat162float(__float2bfloat16_rn(vb.y));
                float gz = __bfloat162float(__float2bfloat16_rn(vb.z));
                float gw = __bfloat162float(__float2bfloat16_rn(vb.w));
                *(uint32_t*)&skh[row * ST + c4]     = packbf(gx, gy);
                *(uint32_t*)&skh[row * ST + c4 + 2] = packbf(gz, gw);
                *(uint32_t*)&skl[row * ST + c4]     = packbf(vb.x - gx, vb.y - gy);
                *(uint32_t*)&skl[row * ST + c4 + 2] = packbf(vb.z - gz, vb.w - gw);
            }
            __syncthreads();
#pragma unroll
            for (int kk = 0; kk < 32; kk += 16) {
                uint32_t ah[4][4], al[4][4], bh2[4][2], bl2[4][2];
#pragma unroll
                for (int mt = 0; mt < 4; mt++) {
                    int m = wrow + mt * 16 + g;
                    ah[mt][0] = *(const uint32_t*)&sqh[(m    ) * ST + kk + 2 * t    ];
                    ah[mt][1] = *(const uint32_t*)&sqh[(m + 8) * ST + kk + 2 * t    ];
                    ah[mt][2] = *(const uint32_t*)&sqh[(m    ) * ST + kk + 2 * t + 8];
                    ah[mt][3] = *(const uint32_t*)&sqh[(m + 8) * ST + kk + 2 * t + 8];
                    al[mt][0] = *(const uint32_t*)&sql[(m    ) * ST + kk + 2 * t    ];
                    al[mt][1] = *(const uint32_t*)&sql[(m + 8) * ST + kk + 2 * t    ];
                    al[mt][2] = *(const uint32_t*)&sql[(m    ) * ST + kk + 2 * t + 8];
                    al[mt][3] = *(const uint32_t*)&sql[(m + 8) * ST + kk + 2 * t + 8];
                }
#pragma unroll
                for (int nt = 0; nt < 4; nt++) {
                    int n = wcol + nt * 8 + g;
                    bh2[nt][0] = *(const uint32_t*)&skh[n * ST + kk + 2 * t    ];
                    bh2[nt][1] = *(const uint32_t*)&skh[n * ST + kk + 2 * t + 8];
                    bl2[nt][0] = *(const uint32_t*)&skl[n * ST + kk + 2 * t    ];
                    bl2[nt][1] = *(const uint32_t*)&skl[n * ST + kk + 2 * t + 8];
                }
#pragma unroll
                for (int mt = 0; mt < 4; mt++)
#pragma unroll
                    for (int nt = 0; nt < 4; nt++) {
                        mma16816(s[mt][nt], ah[mt], bh2[nt]);
                        mma16816(s[mt][nt], al[mt], bh2[nt]);
                        mma16816(s[mt][nt], ah[mt], bl2[nt]);
                    }
            }
            __syncthreads();
        }

        // ---------- load V^T tile (hi/lo), 128 x 128, stride PST ----------
#pragma unroll
        for (int l = 0; l < 8; l++) {
            int seg = tid + l * 256;
            int row = seg >> 4;             // d 0..127
            int cs  = (seg & 15) * 8;       // col offset in elems
            *(uint4*)&Svh[row * PST + cs] = *(const uint4*)&Vh[(size_t)row * Ss + n0 + cs];
            *(uint4*)&Svl[row * PST + cs] = *(const uint4*)&Vl[(size_t)row * Ss + n0 + cs];
        }

        // ---------- scale + causal mask + tile row-max ----------
        float tstat[8];
#pragma unroll
        for (int mt = 0; mt < 4; mt++) {
#pragma unroll
            for (int half = 0; half < 2; half++) {
                int rl = wrow + mt * 16 + g + half * 8;
                float mx = -INFINITY;
#pragma unroll
                for (int nt = 0; nt < 4; nt++) {
#pragma unroll
                    for (int j = 0; j < 2; j++) {
                        int cl = wcol + nt * 8 + 2 * t + j;
                        float sv = s[mt][nt][half * 2 + j] * scale;
                        bool ok = (n0 + cl) <= (m0 + rl);
                        sv = ok ? sv : -INFINITY;
                        s[mt][nt][half * 2 + j] = sv;
                        mx = fmaxf(mx, sv);
                    }
                }
                mx = fmaxf(mx, __shfl_xor_sync(0xffffffffu, mx, 1));
                mx = fmaxf(mx, __shfl_xor_sync(0xffffffffu, mx, 2));
                tstat[mt * 2 + half] = mx;
            }
        }
        if (t == 0) {
#pragma unroll
            for (int mt = 0; mt < 4; mt++)
#pragma unroll
                for (int half = 0; half < 2; half++) {
                    int rl = wrow + mt * 16 + g + half * 8;
                    red[rl * 4 + wc] = tstat[mt * 2 + half];
                }
        }
        __syncthreads();

        float Mn[8], alpha[8];
#pragma unroll
        for (int mt = 0; mt < 4; mt++) {
#pragma unroll
            for (int half = 0; half < 2; half++) {
                int i = mt * 2 + half;
                int rl = wrow + mt * 16 + g + half * 8;
                float tm = fmaxf(fmaxf(red[rl * 4 + 0], red[rl * 4 + 1]),
                                 fmaxf(red[rl * 4 + 2], red[rl * 4 + 3]));
                Mn[i] = fmaxf(M[i], tm);
                alpha[i] = expf(M[i] - Mn[i]);   // exp(-inf) = 0 on first tile
                M[i] = Mn[i];
            }
        }
        __syncthreads();   // red about to be reused for sums

        // ---------- p = exp(s - M), write P hi/lo to smem, row sums ----------
#pragma unroll
        for (int mt = 0; mt < 4; mt++) {
#pragma unroll
            for (int half = 0; half < 2; half++) {
                int i = mt * 2 + half;
                int rl = wrow + mt * 16 + g + half * 8;
                float sm = 0.f;
                float p0 = expf(s[mt][0][half * 2] - M[i]);   // placeholder init
                (void)p0;
#pragma unroll
                for (int nt = 0; nt < 4; nt++) {
                    float pa = expf(s[mt][nt][half * 2 + 0] - M[i]);
                    float pb = expf(s[mt][nt][half * 2 + 1] - M[i]);
                    sm += pa + pb;
                    float ha = __bfloat162float(__float2bfloat16_rn(pa));
                    float hb = __bfloat162float(__float2bfloat16_rn(pb));
                    int cl = wcol + nt * 8 + 2 * t;
                    *(uint32_t*)&Ph[rl * PST + cl] = packbf(ha, hb);
                    *(uint32_t*)&Pl[rl * PST + cl] = packbf(pa - ha, pb - hb);
                }
                sm += __shfl_xor_sync(0xffffffffu, sm, 1);
                sm += __shfl_xor_sync(0xffffffffu, sm, 2);
                tstat[i] = sm;
            }
        }
        if (t == 0) {
#pragma unroll
            for (int mt = 0; mt < 4; mt++)
#pragma unroll
                for (int half = 0; half < 2; half++) {
                    int rl = wrow + mt * 16 + g + half * 8;
                    red[rl * 4 + wc] = tstat[mt * 2 + half];
                }
        }
        __syncthreads();

#pragma unroll
        for (int mt = 0; mt < 4; mt++) {
#pragma unroll
            for (int half = 0; half < 2; half++) {
                int i = mt * 2 + half;
                int rl = wrow + mt * 16 + g + half * 8;
                float rs = red[rl * 4 + 0] + red[rl * 4 + 1] +
                           red[rl * 4 + 2] + red[rl * 4 + 3];
                L[i] = L[i] * alpha[i] + rs;
            }
        }
        // rescale O accumulator
#pragma unroll
        for (int mt = 0; mt < 4; mt++)
#pragma unroll
            for (int nt = 0; nt < 4; nt++) {
                oacc[mt][nt][0] *= alpha[mt * 2 + 0];
                oacc[mt][nt][1] *= alpha[mt * 2 + 0];
                oacc[mt][nt][2] *= alpha[mt * 2 + 1];
                oacc[mt][nt][3] *= alpha[mt * 2 + 1];
            }

        // ---------- PV: O += P . V^T ----------
#pragma unroll
        for (int kk = 0; kk < 128; kk += 16) {
            uint32_t ah[4][4], al[4][4], bh2[4][2], bl2[4][2];
#pragma unroll
            for (int mt = 0; mt < 4; mt++) {
                int m = wrow + mt * 16 + g;
                ah[mt][0] = *(const uint32_t*)&Ph[(m    ) * PST + kk + 2 * t    ];
                ah[mt][1] = *(const uint32_t*)&Ph[(m + 8) * PST + kk + 2 * t    ];
                ah[mt][2] = *(const uint32_t*)&Ph[(m    ) * PST + kk + 2 * t + 8];
                ah[mt][3] = *(const uint32_t*)&Ph[(m + 8) * PST + kk + 2 * t + 8];
                al[mt][0] = *(const uint32_t*)&Pl[(m    ) * PST + kk + 2 * t    ];
                al[mt][1] = *(const uint32_t*)&Pl[(m + 8) * PST + kk + 2 * t    ];
                al[mt][2] = *(const uint32_t*)&Pl[(m    ) * PST + kk + 2 * t + 8];
                al[mt][3] = *(const uint32_t*)&Pl[(m + 8) * PST + kk + 2 * t + 8];
            }
#pragma unroll
            for (int nt = 0; nt < 4; nt++) {
                int n = wcol + nt * 8 + g;
                bh2[nt][0] = *(const uint32_t*)&Svh[n * PST + kk + 2 * t    ];
                bh2[nt][1] = *(const uint32_t*)&Svh[n * PST + kk + 2 * t + 8];
                bl2[nt][0] = *(const uint32_t*)&Svl[n * PST + kk + 2 * t    ];
                bl2[nt][1] = *(const uint32_t*)&Svl[n * PST + kk + 2 * t + 8];
            }
#pragma unroll
            for (int mt = 0; mt < 4; mt++)
#pragma unroll
                for (int nt = 0; nt < 4; nt++) {
                    mma16816(oacc[mt][nt], ah[mt], bh2[nt]);
                    mma16816(oacc[mt][nt], al[mt], bh2[nt]);
                    mma16816(oacc[mt][nt], ah[mt], bl2[nt]);
                }
        }
        __syncthreads();
    }

    // ---------- epilogue: O /= L, write hi/lo bf16 planes ----------
    float inv[8];
#pragma unroll
    for (int i = 0; i < 8; i++) inv[i] = 1.f / L[i];
#pragma unroll
    for (int mt = 0; mt < 4; mt++) {
#pragma unroll
        for (int nt = 0; nt < 4; nt++) {
            int m = m0 + wrow + mt * 16 + g;
            int n = wcol + nt * 8 + 2 * t;
            float v0 = oacc[mt][nt][0] * inv[mt * 2 + 0];
            float v1 = oacc[mt][nt][1] * inv[mt * 2 + 0];
            float h0 = __bfloat162float(__float2bfloat16_rn(v0));
            float h1 = __bfloat162float(__float2bfloat16_rn(v1));
            *(uint32_t*)&Ohi[(size_t)m * QD + n] = packbf(h0, h1);
            *(uint32_t*)&Olo[(size_t)m * QD + n] = packbf(v0 - h0, v1 - h1);

            float v2 = oacc[mt][nt][2] * inv[mt * 2 + 1];
            float v3 = oacc[mt][nt][3] * inv[mt * 2 + 1];
            float h2 = __bfloat162float(__float2bfloat16_rn(v2));
            float h3 = __bfloat162float(__float2bfloat16_rn(v3));
            *(uint32_t*)&Ohi[(size_t)(m + 8) * QD + n] = packbf(h2, h3);
            *(uint32_t*)&Olo[(size_t)(m + 8) * QD + n] = packbf(v2 - h2, v3 - h3);
        }
    }
}

// ---------------- launch ----------------
extern "C" void kernel_launch(void* const* d_in, const int* in_sizes, int n_in,
                              void* d_out, int out_size)
{
    const float* hidden = nullptr;
    const float* big16[2] = {nullptr, nullptr};
    const float* sml4[2]  = {nullptr, nullptr};
    const int*   posid = nullptr;
    int hidden_idx = -1, nb = 0, ns = 0;
    for (int i = 0; i < n_in; i++) {
        if (in_sizes[i] == 8388608)               { hidden = (const float*)d_in[i]; hidden_idx = i; }
        else if (in_sizes[i] == 16777216 && nb<2) { big16[nb++] = (const float*)d_in[i]; }
        else if (in_sizes[i] == 4194304  && ns<2) { sml4[ns++]  = (const float*)d_in[i]; }
        else if (in_sizes[i] == 2048)             { posid = (const int*)d_in[i]; }
    }
    const float* Wq = (hidden_idx == 0) ? big16[0] : big16[1];
    const float* Wo = (hidden_idx == 0) ? big16[1] : big16[0];
    const float* Wk = sml4[0];
    const float* Wv = sml4[1];
    float* out = (float*)d_out;

    void *pq, *pk, *pv, *pahi, *palo, *pwq, *pwk, *pwv, *pwo;
    cudaGetSymbolAddress(&pq, g_q);
    cudaGetSymbolAddress(&pk, g_k);
    cudaGetSymbolAddress(&pv, g_v);
    cudaGetSymbolAddress(&pahi, g_ahi);
    cudaGetSymbolAddress(&palo, g_alo);
    cudaGetSymbolAddress(&pwq, g_wq);
    cudaGetSymbolAddress(&pwk, g_wk);
    cudaGetSymbolAddress(&pwv, g_wv);
    cudaGetSymbolAddress(&pwo, g_wo);

    cudaFuncSetAttribute(gemm_mma2, cudaFuncAttributeMaxDynamicSharedMemorySize, GM_SMEM);
    cudaFuncSetAttribute(flash_mma, cudaFuncAttributeMaxDynamicSharedMemorySize, FL_SMEM);

    const size_t nQ4 = (size_t)QD * Hh / 4;
    const size_t nK4 = (size_t)KVD * Hh / 4;
    const size_t nO4 = (size_t)Hh * QD / 4;
    const size_t nH4 = (size_t)MTOK * Hh / 4;

    cudaStream_t s2;
    cudaEvent_t ev0, evK, evV, evO, evVg, evVS;
    cudaStreamCreateWithFlags(&s2, cudaStreamNonBlocking);
    cudaEventCreateWithFlags(&ev0, cudaEventDisableTiming);
    cudaEventCreateWithFlags(&evK, cudaEventDisableTiming);
    cudaEventCreateWithFlags(&evV, cudaEventDisableTiming);
    cudaEventCreateWithFlags(&evO, cudaEventDisableTiming);
    cudaEventCreateWithFlags(&evVg, cudaEventDisableTiming);
    cudaEventCreateWithFlags(&evVS, cudaEventDisableTiming);

    init_kernel<<<1, 32>>>();
    cudaEventRecord(ev0, 0);
    cudaStreamWaitEvent(s2, ev0, 0);

    // side stream: K/V/O weight preprocessing
    abssum_kernel<<<2048, 256, 0, s2>>>((const float4*)Wk, nK4, 1);
    quantize_kernel<<<4096, 256, 0, s2>>>((const float4*)Wk, (__nv_bfloat162*)pwk, nK4, 1);
    cudaEventRecord(evK, s2);
    abssum_kernel<<<2048, 256, 0, s2>>>((const float4*)Wv, nK4, 2);
    quantize_kernel<<<4096, 256, 0, s2>>>((const float4*)Wv, (__nv_bfloat162*)pwv, nK4, 2);
    cudaEventRecord(evV, s2);
    abssum_kernel<<<2048, 256, 0, s2>>>((const float4*)Wo, nO4, 3);
    quantize_kernel<<<4096, 256, 0, s2>>>((const float4*)Wo, (__nv_bfloat162*)pwo, nO4, 3);
    cudaEventRecord(evO, s2);

    // main stream: Q path
    abssum_kernel<<<2048, 256>>>((const float4*)Wq, nQ4, 0);
    quantize_kernel<<<4096, 256>>>((const float4*)Wq, (__nv_bfloat162*)pwq, nQ4, 0);
    split2_kernel<<<4096, 256>>>((const float4*)hidden, (__nv_bfloat162*)pahi,
                                 (__nv_bfloat162*)palo, nH4);
    gemm_mma2<<<dim3(QD / 128, MTOK / 128), 256, GM_SMEM>>>(
        (const __nv_bfloat16*)pahi, (const __nv_bfloat16*)palo,
        (const __nv_bfloat16*)pwq, (float*)pq, QD, Hh, 0);

    cudaStreamWaitEvent(0, evK, 0);
    gemm_mma2<<<dim3(KVD / 128, MTOK / 128), 256, GM_SMEM>>>(
        (const __nv_bfloat16*)pahi, (const __nv_bfloat16*)palo,
        (const __nv_bfloat16*)pwk, (float*)pk, KVD, Hh, 1);
    cudaStreamWaitEvent(0, evV, 0);
    gemm_mma2<<<dim3(KVD / 128, MTOK / 128), 256, GM_SMEM>>>(
        (const __nv_bfloat16*)pahi, (const __nv_bfloat16*)palo,
        (const __nv_bfloat16*)pwv, (float*)pv, KVD, Hh, 2);
    cudaEventRecord(evVg, 0);

    // side stream: V transpose/split overlaps rope
    cudaStreamWaitEvent(s2, evVg, 0);
    vsplit_kernel<<<(int)(((size_t)Bb * NKVh * HDd * Ss + 255) / 256), 256, 0, s2>>>();
    cudaEventRecord(evVS, s2);

    rope_kernel<<<(int)(((size_t)MTOK * NHq * 64 + 255) / 256), 256>>>((float*)pq, NHq, posid);
    rope_kernel<<<(int)(((size_t)MTOK * NKVh * 64 + 255) / 256), 256>>>((float*)pk, NKVh, posid);

    cudaStreamWaitEvent(0, evVS, 0);
    flash_mma<<<dim3(Ss / 128, Bb * NHq), 256, FL_SMEM>>>();

    cudaStreamWaitEvent(0, evO, 0);
    gemm_mma2<<<dim3(Hh / 128, MTOK / 128), 256, GM_SMEM>>>(
        (const __nv_bfloat16*)pahi, (const __nv_bfloat16*)palo,
        (const __nv_bfloat16*)pwo, out, Hh, QD, 3);
}